// round 13
// baseline (speedup 1.0000x reference)
#include <cuda_runtime.h>

// MultiLayerGRU fused: 3 stacked GRU layers, T=1024, B=4096, I=5, H0=15, H1=10, H2=2.
// R12 core (proven 704.5us): one warp per FOUR batches, two f32x2 packed
// pairs, duplicated (w,w) register weights, per-warp double-buffered SMEM
// float4 broadcast (25 LDS.128 + 2 STS.128 + 1 syncwarp per step), geometry
// 256 blocks x 128 thr (4 warps -> proper SMSP spread).
// R13 change: ALL activations via MUFU.TANH.
//   gates: sigma(a) = 0.5*tanh(a/2)+0.5, r/z weights+biases pre-scaled 0.5
//          at pack time -> tanh.approx + FFMA (was FMUL+EX2+FADD+RCP+FMUL).
//   n:     tanh.approx directly.
// Cuts ~44 inst/warp-step, halves MUFU pipe load (24 -> 12 ops/step/warp),
// shortens the serial recurrence tail ~56 cyc.
// Lane roles:
//   lanes  0..14 : layer-0 units     (read slots 27..51)
//   lanes 15..24 : layer-1 units     (read slots  0..24)
//   lanes 25..26 : layer-2 units     (read slots 15..39; store output)
//   lanes 27..31 : x loaders         (publish x; weights 0)
// Wavefront: step s computes h0(s), h1(s-1), h2(s-2).

#define T_STEPS 1024
#define BATCH   4096
#define IN_DIM  5

using u64 = unsigned long long;

__device__ __forceinline__ u64 pack2(float a, float b) {
    u64 r;
    asm("mov.b64 %0, {%1, %2};" : "=l"(r) : "f"(a), "f"(b));
    return r;
}
__device__ __forceinline__ void unpack2(u64 p, float& a, float& b) {
    asm("mov.b64 {%0, %1}, %2;" : "=f"(a), "=f"(b) : "l"(p));
}
__device__ __forceinline__ u64 fma2(u64 a, u64 b, u64 c) {
    u64 d;
    asm("fma.rn.f32x2 %0, %1, %2, %3;" : "=l"(d) : "l"(a), "l"(b), "l"(c));
    return d;
}
__device__ __forceinline__ float tanh_ap(float a) {
    float r;
    asm("tanh.approx.f32 %0, %1;" : "=f"(r) : "f"(a));
    return r;
}

__global__ __launch_bounds__(128, 2)
void gru3_fused_kernel(
    const float* __restrict__ x,
    const float* __restrict__ w_ih0, const float* __restrict__ w_hh0,
    const float* __restrict__ b_ih0, const float* __restrict__ b_hh0,
    const float* __restrict__ w_ih1, const float* __restrict__ w_hh1,
    const float* __restrict__ b_ih1, const float* __restrict__ b_hh1,
    const float* __restrict__ w_ih2, const float* __restrict__ w_hh2,
    const float* __restrict__ b_ih2, const float* __restrict__ b_hh2,
    float* __restrict__ out)
{
    // ---- stage all weights into shared once ----
    __shared__ float sw[1884];
    // per-warp double-buffered broadcast: [warp][parity][32 lanes + 32 dup]
    __shared__ __align__(16) float4 hbuf[4][2][64];
    {
        int t = threadIdx.x;
        for (int i = t; i < 225; i += 128) sw[i]        = w_ih0[i];
        for (int i = t; i < 675; i += 128) sw[225 + i]  = w_hh0[i];
        for (int i = t; i <  45; i += 128) sw[900 + i]  = b_ih0[i];
        for (int i = t; i <  45; i += 128) sw[945 + i]  = b_hh0[i];
        for (int i = t; i < 450; i += 128) sw[990 + i]  = w_ih1[i];
        for (int i = t; i < 300; i += 128) sw[1440 + i] = w_hh1[i];
        for (int i = t; i <  30; i += 128) sw[1740 + i] = b_ih1[i];
        for (int i = t; i <  30; i += 128) sw[1770 + i] = b_hh1[i];
        for (int i = t; i <  60; i += 128) sw[1800 + i] = w_ih2[i];
        for (int i = t; i <  12; i += 128) sw[1860 + i] = w_hh2[i];
        for (int i = t; i <   6; i += 128) sw[1872 + i] = b_ih2[i];
        for (int i = t; i <   6; i += 128) sw[1878 + i] = b_hh2[i];
    }
    __syncthreads();
    const float* s_wih0 = sw;
    const float* s_whh0 = sw + 225;
    const float* s_bih0 = sw + 900;
    const float* s_bhh0 = sw + 945;
    const float* s_wih1 = sw + 990;
    const float* s_whh1 = sw + 1440;
    const float* s_bih1 = sw + 1740;
    const float* s_bhh1 = sw + 1770;
    const float* s_wih2 = sw + 1800;
    const float* s_whh2 = sw + 1860;
    const float* s_bih2 = sw + 1872;
    const float* s_bhh2 = sw + 1878;

    const int lane = threadIdx.x & 31;
    const int wid  = threadIdx.x >> 5;
    const int gw   = blockIdx.x * 4 + wid;
    const int b0   = gw * 4;           // batches b0 .. b0+3

    // ---- per-lane register-resident weights (unified k-loop, k = 0..24) ----
    float wr[25], wz[25], wni[15], wnh[20];
#pragma unroll
    for (int k = 0; k < 25; k++) { wr[k] = 0.f; wz[k] = 0.f; }
#pragma unroll
    for (int k = 0; k < 15; k++) wni[k] = 0.f;
#pragma unroll
    for (int k = 0; k < 20; k++) wnh[k] = 0.f;
    float br = 0.f, bz = 0.f, bni = 0.f, bnh = 0.f;

    if (lane < 15) {
        const int u = lane;
#pragma unroll
        for (int k = 0; k < 5; k++) {
            wr[k]  = s_wih0[u * 5 + k];
            wz[k]  = s_wih0[(15 + u) * 5 + k];
            wni[k] = s_wih0[(30 + u) * 5 + k];
        }
#pragma unroll
        for (int j = 0; j < 15; j++) {
            wr[5 + j]  = s_whh0[u * 15 + j];
            wz[5 + j]  = s_whh0[(15 + u) * 15 + j];
            wnh[j]     = s_whh0[(30 + u) * 15 + j];
        }
        br  = s_bih0[u] + s_bhh0[u];
        bz  = s_bih0[15 + u] + s_bhh0[15 + u];
        bni = s_bih0[30 + u];
        bnh = s_bhh0[30 + u];
    } else if (lane < 25) {
        const int u = lane - 15;
#pragma unroll
        for (int k = 0; k < 15; k++) {
            wr[k]  = s_wih1[u * 15 + k];
            wz[k]  = s_wih1[(10 + u) * 15 + k];
            wni[k] = s_wih1[(20 + u) * 15 + k];
        }
#pragma unroll
        for (int j = 0; j < 10; j++) {
            wr[15 + j]  = s_whh1[u * 10 + j];
            wz[15 + j]  = s_whh1[(10 + u) * 10 + j];
            wnh[10 + j] = s_whh1[(20 + u) * 10 + j];
        }
        br  = s_bih1[u] + s_bhh1[u];
        bz  = s_bih1[10 + u] + s_bhh1[10 + u];
        bni = s_bih1[20 + u];
        bnh = s_bhh1[20 + u];
    } else if (lane < 27) {
        const int u = lane - 25;
#pragma unroll
        for (int k = 0; k < 10; k++) {
            wr[k]  = s_wih2[u * 10 + k];
            wz[k]  = s_wih2[(2 + u) * 10 + k];
            wni[k] = s_wih2[(4 + u) * 10 + k];
        }
#pragma unroll
        for (int j = 0; j < 2; j++) {
            wr[10 + j] = s_whh2[u * 2 + j];
            wz[10 + j] = s_whh2[(2 + u) * 2 + j];
            wnh[5 + j] = s_whh2[(4 + u) * 2 + j];
        }
        br  = s_bih2[u] + s_bhh2[u];
        bz  = s_bih2[2 + u] + s_bhh2[2 + u];
        bni = s_bih2[4 + u];
        bnh = s_bhh2[4 + u];
    }

    // duplicate-packed weights (w,w) for f32x2 FMA — shared by both batch pairs.
    // r/z pre-scaled by 0.5: sigma(a) = 0.5*tanh(a/2) + 0.5.
    u64 wr2[25], wz2[25], wni2[15], wnh2[20];
#pragma unroll
    for (int k = 0; k < 25; k++) {
        float hr = 0.5f * wr[k], hz = 0.5f * wz[k];
        wr2[k] = pack2(hr, hr);
        wz2[k] = pack2(hz, hz);
    }
#pragma unroll
    for (int k = 0; k < 15; k++) wni2[k] = pack2(wni[k], wni[k]);
#pragma unroll
    for (int k = 0; k < 20; k++) wnh2[k] = pack2(wnh[k], wnh[k]);
    const u64 br2  = pack2(0.5f * br, 0.5f * br);
    const u64 bz2  = pack2(0.5f * bz, 0.5f * bz);
    const u64 bni2 = pack2(bni, bni);
    const u64 bnh2 = pack2(bnh, bnh);

    // read base per lane class (wrap handled by duplicate store at lane+32)
    const int base = (lane < 15) ? 27 : (lane < 25) ? 0 : (lane < 27) ? 15 : 0;

    // wavefront delay per lane; loader lanes never commit
    const int d = (lane < 15) ? 0 : (lane < 25) ? 1 : (lane < 27) ? 2 : 0x40000000;
    const bool isOut = (lane == 25) || (lane == 26);

    const int feat = (lane >= 27) ? (lane - 27) : 0;
    const float* xp = x + (size_t)b0 * IN_DIM + feat;
    const int u2 = (lane >= 25) ? (lane - 25) : 0;
    float* op = out + (size_t)b0 * 2 + u2;

    float h[4] = {0.f, 0.f, 0.f, 0.f};   // hidden state, 4 batches
    float xn[4] = {0.f, 0.f, 0.f, 0.f};  // prefetched x(t+1)
    u64 sh0 = 0, sh1 = 0;                // packed operands (b0,b1) / (b2,b3)
    if (lane >= 27) {
        sh0 = pack2(xp[0 * IN_DIM], xp[1 * IN_DIM]);             // x(0)
        sh1 = pack2(xp[2 * IN_DIM], xp[3 * IN_DIM]);
#pragma unroll
        for (int j = 0; j < 4; j++) xn[j] = xp[BATCH * IN_DIM + j * IN_DIM];  // x(1)
    }

    const float4* rd0 = &hbuf[wid][0][base];
    const float4* rd1 = &hbuf[wid][1][base];
    float4* wp0 = &hbuf[wid][0][lane];
    float4* wp1 = &hbuf[wid][1][lane];

    // initial publish of (x(0), h=0) into parity 0
    {
        float s0a, s0b, s1a, s1b;
        unpack2(sh0, s0a, s0b);
        unpack2(sh1, s1a, s1b);
        float4 v = make_float4(s0a, s0b, s1a, s1b);
        wp0[0] = v; wp0[32] = v;
    }
    __syncwarp(0xffffffffu);

    auto body = [&](int s, const float4* rd, float4* wp) {
        u64 ar0 = br2, az0 = bz2, ani0 = bni2, anh0 = bnh2;
        u64 ar1 = br2, az1 = bz2, ani1 = bni2, anh1 = bnh2;
#pragma unroll
        for (int k = 0; k < 25; k++) {
            float4 q = rd[k];                 // ld.shared.v4, immediate offset
            u64 v0 = pack2(q.x, q.y);
            u64 v1 = pack2(q.z, q.w);
            ar0 = fma2(wr2[k], v0, ar0);
            ar1 = fma2(wr2[k], v1, ar1);
            az0 = fma2(wz2[k], v0, az0);
            az1 = fma2(wz2[k], v1, az1);
            if (k < 15) { ani0 = fma2(wni2[k], v0, ani0); ani1 = fma2(wni2[k], v1, ani1); }
            if (k >= 5) { anh0 = fma2(wnh2[k - 5], v0, anh0); anh1 = fma2(wnh2[k - 5], v1, anh1); }
        }

        float arf[4], azf[4], anif[4], anhf[4], hn[4];
        unpack2(ar0, arf[0], arf[1]);    unpack2(ar1, arf[2], arf[3]);
        unpack2(az0, azf[0], azf[1]);    unpack2(az1, azf[2], azf[3]);
        unpack2(ani0, anif[0], anif[1]); unpack2(ani1, anif[2], anif[3]);
        unpack2(anh0, anhf[0], anhf[1]); unpack2(anh1, anhf[2], anhf[3]);
#pragma unroll
        for (int j = 0; j < 4; j++) {
            // arf/azf pre-scaled by 0.5: sigma = 0.5*tanh + 0.5
            float r = fmaf(tanh_ap(arf[j]), 0.5f, 0.5f);
            float z = fmaf(tanh_ap(azf[j]), 0.5f, 0.5f);
            float n = tanh_ap(fmaf(r, anhf[j], anif[j]));
            hn[j] = fmaf(z, h[j] - n, n);                        // (1-z)*n + z*h
        }

        bool valid = (s >= d) && (s < T_STEPS + d);
        if (valid) {
#pragma unroll
            for (int j = 0; j < 4; j++) h[j] = hn[j];
        }
        if (valid && isOut) {
            size_t o = (size_t)(s - 2) * (BATCH * 2);
#pragma unroll
            for (int j = 0; j < 4; j++) op[o + j * 2] = hn[j];
        }

        if (lane < 27) {
            sh0 = pack2(h[0], h[1]);
            sh1 = pack2(h[2], h[3]);
        } else {
            sh0 = pack2(xn[0], xn[1]);                           // becomes x(s+1)
            sh1 = pack2(xn[2], xn[3]);
            int t2 = s + 2;
            bool inb = (t2 < T_STEPS);
            size_t xo = (size_t)t2 * (BATCH * IN_DIM);
#pragma unroll
            for (int j = 0; j < 4; j++) xn[j] = inb ? xp[xo + j * IN_DIM] : 0.f;
        }

        float s0a, s0b, s1a, s1b;
        unpack2(sh0, s0a, s0b);
        unpack2(sh1, s1a, s1b);
        float4 v = make_float4(s0a, s0b, s1a, s1b);
        wp[0] = v; wp[32] = v;
        __syncwarp(0xffffffffu);
    };

    // 1026 steps, manual 2x unroll for compile-time buffer parity
    for (int s = 0; s < T_STEPS + 2; s += 2) {
        body(s,     rd0, wp1);
        body(s + 1, rd1, wp0);
    }
}

extern "C" void kernel_launch(void* const* d_in, const int* in_sizes, int n_in,
                              void* d_out, int out_size)
{
    (void)in_sizes; (void)n_in; (void)out_size;
    const float* x     = (const float*)d_in[0];
    const float* w_ih0 = (const float*)d_in[1];
    const float* w_hh0 = (const float*)d_in[2];
    const float* b_ih0 = (const float*)d_in[3];
    const float* b_hh0 = (const float*)d_in[4];
    const float* w_ih1 = (const float*)d_in[5];
    const float* w_hh1 = (const float*)d_in[6];
    const float* b_ih1 = (const float*)d_in[7];
    const float* b_hh1 = (const float*)d_in[8];
    const float* w_ih2 = (const float*)d_in[9];
    const float* w_hh2 = (const float*)d_in[10];
    const float* b_ih2 = (const float*)d_in[11];
    const float* b_hh2 = (const float*)d_in[12];

    // one warp per 4 batch elements: 1024 warps = 256 blocks x 4 warps
    gru3_fused_kernel<<<BATCH / 16, 128>>>(
        x, w_ih0, w_hh0, b_ih0, b_hh0,
        w_ih1, w_hh1, b_ih1, b_hh1,
        w_ih2, w_hh2, b_ih2, b_hh2,
        (float*)d_out);
}

// round 14
// speedup vs baseline: 1.4733x; 1.4733x over previous
#include <cuda_runtime.h>

// MultiLayerGRU fused: 3 stacked GRU layers, T=1024, B=4096, I=5, H0=15, H1=10, H2=2.
// R12 core (proven 704.5us): one warp per FOUR batches, two f32x2 packed
// pairs, duplicated (w,w) register weights, per-warp double-buffered SMEM
// float4 broadcast (25 LDS.128 + 2 STS.128 + 1 syncwarp per step), geometry
// 256 blocks x 128 thr (4 warps -> proper SMSP spread).
// R14 change: epilogue via native MUFU ops only (EX2, RCP; tanh.approx is
// EMULATED on sm_103a - R10/R13 each paid +50% for it).
//   r/z weights+biases pre-scaled by -log2(e):   sigma = rcp(1 + ex2(acc))
//   n  weights+biases pre-scaled by -2*log2(e):  tanh  = 2*rcp(1+ex2(acc)) - 1
// (scaling is linear so it distributes over ani + r*anh with r unscaled).
// Saves ~15 inst/warp-step and shortens the serial r->n chain.
// Lane roles:
//   lanes  0..14 : layer-0 units     (read slots 27..51)
//   lanes 15..24 : layer-1 units     (read slots  0..24)
//   lanes 25..26 : layer-2 units     (read slots 15..39; store output)
//   lanes 27..31 : x loaders         (publish x; weights 0)
// Wavefront: step s computes h0(s), h1(s-1), h2(s-2).

#define T_STEPS 1024
#define BATCH   4096
#define IN_DIM  5

using u64 = unsigned long long;

__device__ __forceinline__ u64 pack2(float a, float b) {
    u64 r;
    asm("mov.b64 %0, {%1, %2};" : "=l"(r) : "f"(a), "f"(b));
    return r;
}
__device__ __forceinline__ void unpack2(u64 p, float& a, float& b) {
    asm("mov.b64 {%0, %1}, %2;" : "=f"(a), "=f"(b) : "l"(p));
}
__device__ __forceinline__ u64 fma2(u64 a, u64 b, u64 c) {
    u64 d;
    asm("fma.rn.f32x2 %0, %1, %2, %3;" : "=l"(d) : "l"(a), "l"(b), "l"(c));
    return d;
}
__device__ __forceinline__ float ex2_(float a) {
    float r;
    asm("ex2.approx.f32 %0, %1;" : "=f"(r) : "f"(a));
    return r;
}
__device__ __forceinline__ float rcp_(float a) {
    float r;
    asm("rcp.approx.f32 %0, %1;" : "=f"(r) : "f"(a));
    return r;
}

__global__ __launch_bounds__(128, 2)
void gru3_fused_kernel(
    const float* __restrict__ x,
    const float* __restrict__ w_ih0, const float* __restrict__ w_hh0,
    const float* __restrict__ b_ih0, const float* __restrict__ b_hh0,
    const float* __restrict__ w_ih1, const float* __restrict__ w_hh1,
    const float* __restrict__ b_ih1, const float* __restrict__ b_hh1,
    const float* __restrict__ w_ih2, const float* __restrict__ w_hh2,
    const float* __restrict__ b_ih2, const float* __restrict__ b_hh2,
    float* __restrict__ out)
{
    // ---- stage all weights into shared once ----
    __shared__ float sw[1884];
    // per-warp double-buffered broadcast: [warp][parity][32 lanes + 32 dup]
    __shared__ __align__(16) float4 hbuf[4][2][64];
    {
        int t = threadIdx.x;
        for (int i = t; i < 225; i += 128) sw[i]        = w_ih0[i];
        for (int i = t; i < 675; i += 128) sw[225 + i]  = w_hh0[i];
        for (int i = t; i <  45; i += 128) sw[900 + i]  = b_ih0[i];
        for (int i = t; i <  45; i += 128) sw[945 + i]  = b_hh0[i];
        for (int i = t; i < 450; i += 128) sw[990 + i]  = w_ih1[i];
        for (int i = t; i < 300; i += 128) sw[1440 + i] = w_hh1[i];
        for (int i = t; i <  30; i += 128) sw[1740 + i] = b_ih1[i];
        for (int i = t; i <  30; i += 128) sw[1770 + i] = b_hh1[i];
        for (int i = t; i <  60; i += 128) sw[1800 + i] = w_ih2[i];
        for (int i = t; i <  12; i += 128) sw[1860 + i] = w_hh2[i];
        for (int i = t; i <   6; i += 128) sw[1872 + i] = b_ih2[i];
        for (int i = t; i <   6; i += 128) sw[1878 + i] = b_hh2[i];
    }
    __syncthreads();
    const float* s_wih0 = sw;
    const float* s_whh0 = sw + 225;
    const float* s_bih0 = sw + 900;
    const float* s_bhh0 = sw + 945;
    const float* s_wih1 = sw + 990;
    const float* s_whh1 = sw + 1440;
    const float* s_bih1 = sw + 1740;
    const float* s_bhh1 = sw + 1770;
    const float* s_wih2 = sw + 1800;
    const float* s_whh2 = sw + 1860;
    const float* s_bih2 = sw + 1872;
    const float* s_bhh2 = sw + 1878;

    const int lane = threadIdx.x & 31;
    const int wid  = threadIdx.x >> 5;
    const int gw   = blockIdx.x * 4 + wid;
    const int b0   = gw * 4;           // batches b0 .. b0+3

    // ---- per-lane register-resident weights (unified k-loop, k = 0..24) ----
    float wr[25], wz[25], wni[15], wnh[20];
#pragma unroll
    for (int k = 0; k < 25; k++) { wr[k] = 0.f; wz[k] = 0.f; }
#pragma unroll
    for (int k = 0; k < 15; k++) wni[k] = 0.f;
#pragma unroll
    for (int k = 0; k < 20; k++) wnh[k] = 0.f;
    float br = 0.f, bz = 0.f, bni = 0.f, bnh = 0.f;

    if (lane < 15) {
        const int u = lane;
#pragma unroll
        for (int k = 0; k < 5; k++) {
            wr[k]  = s_wih0[u * 5 + k];
            wz[k]  = s_wih0[(15 + u) * 5 + k];
            wni[k] = s_wih0[(30 + u) * 5 + k];
        }
#pragma unroll
        for (int j = 0; j < 15; j++) {
            wr[5 + j]  = s_whh0[u * 15 + j];
            wz[5 + j]  = s_whh0[(15 + u) * 15 + j];
            wnh[j]     = s_whh0[(30 + u) * 15 + j];
        }
        br  = s_bih0[u] + s_bhh0[u];
        bz  = s_bih0[15 + u] + s_bhh0[15 + u];
        bni = s_bih0[30 + u];
        bnh = s_bhh0[30 + u];
    } else if (lane < 25) {
        const int u = lane - 15;
#pragma unroll
        for (int k = 0; k < 15; k++) {
            wr[k]  = s_wih1[u * 15 + k];
            wz[k]  = s_wih1[(10 + u) * 15 + k];
            wni[k] = s_wih1[(20 + u) * 15 + k];
        }
#pragma unroll
        for (int j = 0; j < 10; j++) {
            wr[15 + j]  = s_whh1[u * 10 + j];
            wz[15 + j]  = s_whh1[(10 + u) * 10 + j];
            wnh[10 + j] = s_whh1[(20 + u) * 10 + j];
        }
        br  = s_bih1[u] + s_bhh1[u];
        bz  = s_bih1[10 + u] + s_bhh1[10 + u];
        bni = s_bih1[20 + u];
        bnh = s_bhh1[20 + u];
    } else if (lane < 27) {
        const int u = lane - 25;
#pragma unroll
        for (int k = 0; k < 10; k++) {
            wr[k]  = s_wih2[u * 10 + k];
            wz[k]  = s_wih2[(2 + u) * 10 + k];
            wni[k] = s_wih2[(4 + u) * 10 + k];
        }
#pragma unroll
        for (int j = 0; j < 2; j++) {
            wr[10 + j] = s_whh2[u * 2 + j];
            wz[10 + j] = s_whh2[(2 + u) * 2 + j];
            wnh[5 + j] = s_whh2[(4 + u) * 2 + j];
        }
        br  = s_bih2[u] + s_bhh2[u];
        bz  = s_bih2[2 + u] + s_bhh2[2 + u];
        bni = s_bih2[4 + u];
        bnh = s_bhh2[4 + u];
    }

    // duplicate-packed weights (w,w), pre-scaled for the MUFU-native epilogue:
    //   r/z by -log2(e)  -> sigma = rcp(1 + ex2(acc))
    //   n   by -2log2(e) -> tanh  = 2*rcp(1 + ex2(acc)) - 1
    const float NL  = -1.4426950408889634f;   // -log2(e)
    const float N2L = -2.8853900817779268f;   // -2*log2(e)
    u64 wr2[25], wz2[25], wni2[15], wnh2[20];
#pragma unroll
    for (int k = 0; k < 25; k++) {
        float sr = NL * wr[k], sz = NL * wz[k];
        wr2[k] = pack2(sr, sr);
        wz2[k] = pack2(sz, sz);
    }
#pragma unroll
    for (int k = 0; k < 15; k++) { float s = N2L * wni[k]; wni2[k] = pack2(s, s); }
#pragma unroll
    for (int k = 0; k < 20; k++) { float s = N2L * wnh[k]; wnh2[k] = pack2(s, s); }
    const u64 br2  = pack2(NL * br,  NL * br);
    const u64 bz2  = pack2(NL * bz,  NL * bz);
    const u64 bni2 = pack2(N2L * bni, N2L * bni);
    const u64 bnh2 = pack2(N2L * bnh, N2L * bnh);

    // read base per lane class (wrap handled by duplicate store at lane+32)
    const int base = (lane < 15) ? 27 : (lane < 25) ? 0 : (lane < 27) ? 15 : 0;

    // wavefront delay per lane; loader lanes never commit
    const int d = (lane < 15) ? 0 : (lane < 25) ? 1 : (lane < 27) ? 2 : 0x40000000;
    const bool isOut = (lane == 25) || (lane == 26);

    const int feat = (lane >= 27) ? (lane - 27) : 0;
    const float* xp = x + (size_t)b0 * IN_DIM + feat;
    const int u2 = (lane >= 25) ? (lane - 25) : 0;
    float* op = out + (size_t)b0 * 2 + u2;

    float h[4] = {0.f, 0.f, 0.f, 0.f};   // hidden state, 4 batches
    float xn[4] = {0.f, 0.f, 0.f, 0.f};  // prefetched x(t+1)
    u64 sh0 = 0, sh1 = 0;                // packed operands (b0,b1) / (b2,b3)
    if (lane >= 27) {
        sh0 = pack2(xp[0 * IN_DIM], xp[1 * IN_DIM]);             // x(0)
        sh1 = pack2(xp[2 * IN_DIM], xp[3 * IN_DIM]);
#pragma unroll
        for (int j = 0; j < 4; j++) xn[j] = xp[BATCH * IN_DIM + j * IN_DIM];  // x(1)
    }

    const float4* rd0 = &hbuf[wid][0][base];
    const float4* rd1 = &hbuf[wid][1][base];
    float4* wp0 = &hbuf[wid][0][lane];
    float4* wp1 = &hbuf[wid][1][lane];

    // initial publish of (x(0), h=0) into parity 0
    {
        float s0a, s0b, s1a, s1b;
        unpack2(sh0, s0a, s0b);
        unpack2(sh1, s1a, s1b);
        float4 v = make_float4(s0a, s0b, s1a, s1b);
        wp0[0] = v; wp0[32] = v;
    }
    __syncwarp(0xffffffffu);

    auto body = [&](int s, const float4* rd, float4* wp) {
        u64 ar0 = br2, az0 = bz2, ani0 = bni2, anh0 = bnh2;
        u64 ar1 = br2, az1 = bz2, ani1 = bni2, anh1 = bnh2;
#pragma unroll
        for (int k = 0; k < 25; k++) {
            float4 q = rd[k];                 // ld.shared.v4, immediate offset
            u64 v0 = pack2(q.x, q.y);
            u64 v1 = pack2(q.z, q.w);
            ar0 = fma2(wr2[k], v0, ar0);
            ar1 = fma2(wr2[k], v1, ar1);
            az0 = fma2(wz2[k], v0, az0);
            az1 = fma2(wz2[k], v1, az1);
            if (k < 15) { ani0 = fma2(wni2[k], v0, ani0); ani1 = fma2(wni2[k], v1, ani1); }
            if (k >= 5) { anh0 = fma2(wnh2[k - 5], v0, anh0); anh1 = fma2(wnh2[k - 5], v1, anh1); }
        }

        float arf[4], azf[4], anif[4], anhf[4], hn[4];
        unpack2(ar0, arf[0], arf[1]);    unpack2(ar1, arf[2], arf[3]);
        unpack2(az0, azf[0], azf[1]);    unpack2(az1, azf[2], azf[3]);
        unpack2(ani0, anif[0], anif[1]); unpack2(ani1, anif[2], anif[3]);
        unpack2(anh0, anhf[0], anhf[1]); unpack2(anh1, anhf[2], anhf[3]);
#pragma unroll
        for (int j = 0; j < 4; j++) {
            // acc pre-scaled: sigma = rcp(1+ex2(acc)); tanh = 2*rcp(1+ex2(acc))-1
            float r = rcp_(1.0f + ex2_(arf[j]));
            float z = rcp_(1.0f + ex2_(azf[j]));
            float n = fmaf(2.0f, rcp_(1.0f + ex2_(fmaf(r, anhf[j], anif[j]))), -1.0f);
            hn[j] = fmaf(z, h[j] - n, n);                        // (1-z)*n + z*h
        }

        bool valid = (s >= d) && (s < T_STEPS + d);
        if (valid) {
#pragma unroll
            for (int j = 0; j < 4; j++) h[j] = hn[j];
        }
        if (valid && isOut) {
            size_t o = (size_t)(s - 2) * (BATCH * 2);
#pragma unroll
            for (int j = 0; j < 4; j++) op[o + j * 2] = hn[j];
        }

        if (lane < 27) {
            sh0 = pack2(h[0], h[1]);
            sh1 = pack2(h[2], h[3]);
        } else {
            sh0 = pack2(xn[0], xn[1]);                           // becomes x(s+1)
            sh1 = pack2(xn[2], xn[3]);
            int t2 = s + 2;
            bool inb = (t2 < T_STEPS);
            size_t xo = (size_t)t2 * (BATCH * IN_DIM);
#pragma unroll
            for (int j = 0; j < 4; j++) xn[j] = inb ? xp[xo + j * IN_DIM] : 0.f;
        }

        float s0a, s0b, s1a, s1b;
        unpack2(sh0, s0a, s0b);
        unpack2(sh1, s1a, s1b);
        float4 v = make_float4(s0a, s0b, s1a, s1b);
        wp[0] = v; wp[32] = v;
        __syncwarp(0xffffffffu);
    };

    // 1026 steps, manual 2x unroll for compile-time buffer parity
    for (int s = 0; s < T_STEPS + 2; s += 2) {
        body(s,     rd0, wp1);
        body(s + 1, rd1, wp0);
    }
}

extern "C" void kernel_launch(void* const* d_in, const int* in_sizes, int n_in,
                              void* d_out, int out_size)
{
    (void)in_sizes; (void)n_in; (void)out_size;
    const float* x     = (const float*)d_in[0];
    const float* w_ih0 = (const float*)d_in[1];
    const float* w_hh0 = (const float*)d_in[2];
    const float* b_ih0 = (const float*)d_in[3];
    const float* b_hh0 = (const float*)d_in[4];
    const float* w_ih1 = (const float*)d_in[5];
    const float* w_hh1 = (const float*)d_in[6];
    const float* b_ih1 = (const float*)d_in[7];
    const float* b_hh1 = (const float*)d_in[8];
    const float* w_ih2 = (const float*)d_in[9];
    const float* w_hh2 = (const float*)d_in[10];
    const float* b_ih2 = (const float*)d_in[11];
    const float* b_hh2 = (const float*)d_in[12];

    // one warp per 4 batch elements: 1024 warps = 256 blocks x 4 warps
    gru3_fused_kernel<<<BATCH / 16, 128>>>(
        x, w_ih0, w_hh0, b_ih0, b_hh0,
        w_ih1, w_hh1, b_ih1, b_hh1,
        w_ih2, w_hh2, b_ih2, b_hh2,
        (float*)d_out);
}